// round 2
// baseline (speedup 1.0000x reference)
#include <cuda_runtime.h>
#include <cuda_bf16.h>

#define KC   512
#define DD   64
#define HW   4096
#define NB   32
#define NPIX (NB * HW)
#define XNUM (NPIX * DD)

__device__ int    g_idx[NPIX];
__device__ double g_losssum;

extern __shared__ float smem[];

// Emulate XLA:GPU row-reduce tree for 64 elements, vec=2:
//   partial[t] = fl(fl(v[2t]^2) + fl(v[2t+1]^2)),  t = 0..31
//   butterfly: off = 16,8,4,2,1:  partial[l] = fl(partial[l] + partial[l+off])
__device__ __forceinline__ float sumsq_tree64(const float* v) {
    float p[32];
#pragma unroll
    for (int t = 0; t < 32; t++) {
        float a = __fmul_rn(v[2 * t], v[2 * t]);
        float b = __fmul_rn(v[2 * t + 1], v[2 * t + 1]);
        p[t] = __fadd_rn(a, b);
    }
#pragma unroll
    for (int off = 16; off >= 1; off >>= 1) {
#pragma unroll
        for (int l = 0; l < 16; l++) {
            if (l < off) p[l] = __fadd_rn(p[l], p[l + off]);
        }
    }
    return p[0];
}

// ---------------------------------------------------------------------------
// Kernel A: per-pixel argmin over 512 codes, replicating the reference's fp32
// rounding: dist_k = fl( fl(xsq + wsq_k) - 2*dot_k ), first-min tie-break.
// ---------------------------------------------------------------------------
__global__ void __launch_bounds__(256, 1)
vq_argmin(const float* __restrict__ x, const float* __restrict__ w,
          int* __restrict__ gidx, float* __restrict__ out_idx)
{
    float* sw  = smem;             // [KC*DD]
    float* se2 = smem + KC * DD;   // [KC]
    const int tid = threadIdx.x;

    {   // cooperative codebook load
        const float4* w4  = (const float4*)w;
        float4*       sw4 = (float4*)sw;
        for (int i = tid; i < KC * DD / 4; i += blockDim.x) sw4[i] = w4[i];
    }
    __syncthreads();

    // per-code squared norm with the SAME reduction tree as the reference
    for (int k = tid; k < KC; k += blockDim.x) {
        float wr[DD];
#pragma unroll
        for (int d = 0; d < DD; d++) wr[d] = sw[k * DD + d];
        se2[k] = sumsq_tree64(wr);
    }
    __syncthreads();

    const int n  = blockIdx.x * blockDim.x + tid;
    const int b  = n >> 12;
    const int hw = n & 4095;
    const float* xp = x + (size_t)b * DD * HW + hw;

    float xr[DD];
#pragma unroll
    for (int d = 0; d < DD; d++) xr[d] = xp[(size_t)d * HW];

    const float xsq = sumsq_tree64(xr);

    float best = 3.4e38f;
    int   bi   = 0;
    for (int k = 0; k < KC; k += 4) {
        const float4* w0 = (const float4*)(sw + (k + 0) * DD);
        const float4* w1 = (const float4*)(sw + (k + 1) * DD);
        const float4* w2 = (const float4*)(sw + (k + 2) * DD);
        const float4* w3 = (const float4*)(sw + (k + 3) * DD);
        float a0 = 0.f, a1 = 0.f, a2 = 0.f, a3 = 0.f;
#pragma unroll
        for (int j = 0; j < DD / 4; j++) {
            float4 v0 = w0[j], v1 = w1[j], v2 = w2[j], v3 = w3[j];
            // sequential-in-d fp32 accumulation per code (4 independent chains)
            a0 = __fmaf_rn(xr[4 * j + 0], v0.x, a0);
            a1 = __fmaf_rn(xr[4 * j + 0], v1.x, a1);
            a2 = __fmaf_rn(xr[4 * j + 0], v2.x, a2);
            a3 = __fmaf_rn(xr[4 * j + 0], v3.x, a3);
            a0 = __fmaf_rn(xr[4 * j + 1], v0.y, a0);
            a1 = __fmaf_rn(xr[4 * j + 1], v1.y, a1);
            a2 = __fmaf_rn(xr[4 * j + 1], v2.y, a2);
            a3 = __fmaf_rn(xr[4 * j + 1], v3.y, a3);
            a0 = __fmaf_rn(xr[4 * j + 2], v0.z, a0);
            a1 = __fmaf_rn(xr[4 * j + 2], v1.z, a1);
            a2 = __fmaf_rn(xr[4 * j + 2], v2.z, a2);
            a3 = __fmaf_rn(xr[4 * j + 2], v3.z, a3);
            a0 = __fmaf_rn(xr[4 * j + 3], v0.w, a0);
            a1 = __fmaf_rn(xr[4 * j + 3], v1.w, a1);
            a2 = __fmaf_rn(xr[4 * j + 3], v2.w, a2);
            a3 = __fmaf_rn(xr[4 * j + 3], v3.w, a3);
        }
        // dist = fl( fl(xsq + wsq) - fl(2*dot) ), then first-min argmin
        float d0 = __fsub_rn(__fadd_rn(xsq, se2[k + 0]), __fadd_rn(a0, a0));
        float d1 = __fsub_rn(__fadd_rn(xsq, se2[k + 1]), __fadd_rn(a1, a1));
        float d2 = __fsub_rn(__fadd_rn(xsq, se2[k + 2]), __fadd_rn(a2, a2));
        float d3 = __fsub_rn(__fadd_rn(xsq, se2[k + 3]), __fadd_rn(a3, a3));
        if (d0 < best) { best = d0; bi = k + 0; }
        if (d1 < best) { best = d1; bi = k + 1; }
        if (d2 < best) { best = d2; bi = k + 2; }
        if (d3 < best) { best = d3; bi = k + 3; }
    }
    gidx[n]    = bi;
    out_idx[n] = (float)bi;
}

// ---------------------------------------------------------------------------
// Kernel B: quantized NCHW output with straight-through rounding replicated,
// one-hot scatter, loss accumulation.
// ---------------------------------------------------------------------------
__global__ void __launch_bounds__(256, 1)
vq_scatter(const float* __restrict__ x, const float* __restrict__ w,
           const int* __restrict__ gidx,
           float* __restrict__ out_q, float* __restrict__ out_enc,
           double* __restrict__ losssum)
{
    float* sw = smem;  // [KC * 65] padded
    const int tid = threadIdx.x;

    for (int i = tid; i < KC * DD; i += blockDim.x) {
        const int k = i >> 6;
        const int d = i & 63;
        sw[k * 65 + d] = w[i];
    }
    __syncthreads();

    const int n  = blockIdx.x * blockDim.x + tid;
    const int k  = gidx[n];
    const int b  = n >> 12;
    const int hw = n & 4095;
    const float* xp = x     + (size_t)b * DD * HW + hw;
    float*       qp = out_q + (size_t)b * DD * HW + hw;
    const float* wr = sw + k * 65;

    float s = 0.f;
#pragma unroll
    for (int d = 0; d < DD; d++) {
        const float xv = xp[(size_t)d * HW];
        const float qv = wr[d];
        const float df = __fsub_rn(qv, xv);         // fl(q - x)
        qp[(size_t)d * HW] = __fadd_rn(xv, df);     // fl(x + fl(q - x))
        s = fmaf(df, df, s);
    }

    out_enc[(size_t)n * KC + k] = 1.0f;

#pragma unroll
    for (int off = 16; off; off >>= 1) s += __shfl_down_sync(0xffffffffu, s, off);
    __shared__ float sred[8];
    if ((tid & 31) == 0) sred[tid >> 5] = s;
    __syncthreads();
    if (tid < 8) {
        float v = sred[tid];
#pragma unroll
        for (int off = 4; off; off >>= 1) v += __shfl_down_sync(0xffu, v, off);
        if (tid == 0) atomicAdd(losssum, (double)v);
    }
}

__global__ void vq_finalize(const double* __restrict__ losssum,
                            float* __restrict__ out_loss)
{
    out_loss[0] = (float)(2.0 * (*losssum) / (double)XNUM);
}

// ---------------------------------------------------------------------------
extern "C" void kernel_launch(void* const* d_in, const int* in_sizes, int n_in,
                              void* d_out, int out_size)
{
    const float* x = (const float*)d_in[0];   // [32, 64, 64, 64] NCHW
    const float* w = (const float*)d_in[1];   // [512, 64]

    float* out      = (float*)d_out;
    float* out_loss = out;
    float* out_q    = out + 1;
    float* out_enc  = out + 1 + (size_t)XNUM;
    float* out_idx  = out + 1 + (size_t)XNUM + (size_t)NPIX * KC;

    int*    gidx_ptr = nullptr;
    double* loss_ptr = nullptr;
    cudaGetSymbolAddress((void**)&gidx_ptr, g_idx);
    cudaGetSymbolAddress((void**)&loss_ptr, g_losssum);

    const int smem_a = (KC * DD + KC) * (int)sizeof(float);
    const int smem_b = (KC * 65) * (int)sizeof(float);
    cudaFuncSetAttribute(vq_argmin,  cudaFuncAttributeMaxDynamicSharedMemorySize, smem_a);
    cudaFuncSetAttribute(vq_scatter, cudaFuncAttributeMaxDynamicSharedMemorySize, smem_b);

    cudaMemsetAsync(out_enc, 0, (size_t)NPIX * KC * sizeof(float), 0);
    cudaMemsetAsync(loss_ptr, 0, sizeof(double), 0);

    vq_argmin <<<NPIX / 256, 256, smem_a>>>(x, w, gidx_ptr, out_idx);
    vq_scatter<<<NPIX / 256, 256, smem_b>>>(x, w, gidx_ptr, out_q, out_enc, loss_ptr);
    vq_finalize<<<1, 1>>>(loss_ptr, out_loss);
}

// round 3
// speedup vs baseline: 1.1930x; 1.1930x over previous
#include <cuda_runtime.h>
#include <cuda_bf16.h>

#define KC   512
#define DD   64
#define HW   4096
#define NB   32
#define NPIX (NB * HW)
#define XNUM (NPIX * DD)

#define PIX_PER_BLK 256
#define PPT 4            // pixels per thread
#define CPT 8            // codes per thread
#define KTILE 32         // codes per k-tile (4 code-groups * 8)

__device__ int    g_idx[NPIX];
__device__ double g_losssum;

extern __shared__ float smem[];

// Reference fp32 reduction tree for 64 elements (vec=2 + shfl butterfly).
__device__ __forceinline__ float sumsq_tree64(const float* v) {
    float p[32];
#pragma unroll
    for (int t = 0; t < 32; t++) {
        float a = __fmul_rn(v[2 * t], v[2 * t]);
        float b = __fmul_rn(v[2 * t + 1], v[2 * t + 1]);
        p[t] = __fadd_rn(a, b);
    }
#pragma unroll
    for (int off = 16; off >= 1; off >>= 1) {
#pragma unroll
        for (int l = 0; l < 16; l++) {
            if (l < off) p[l] = __fadd_rn(p[l], p[l + off]);
        }
    }
    return p[0];
}

// ---------------------------------------------------------------------------
// Kernel A: register-tiled argmin. Block = 256 threads = 64 pixel-groups x 4
// code-groups. Each thread: 4 pixels x 8 codes accumulator tile.
// Decision-path rounding identical to the bit-exact round-2 kernel.
// ---------------------------------------------------------------------------
__global__ void __launch_bounds__(256, 1)
vq_argmin(const float* __restrict__ x, const float* __restrict__ w,
          int* __restrict__ gidx, float* __restrict__ out_idx)
{
    float* w_s  = smem;                       // [512*64]
    float* x_s  = w_s + KC * DD;              // [64][256] d-major
    float* se2  = x_s + DD * PIX_PER_BLK;     // [512]
    float* xsq  = se2 + KC;                   // [256]
    float* redd = xsq + PIX_PER_BLK;          // [4*256]
    int*   redi = (int*)(redd + 4 * PIX_PER_BLK); // [4*256]

    const int tid    = threadIdx.x;
    const int pix_t  = tid & 63;              // 0..63
    const int code_t = tid >> 6;              // 0..3
    const int n0     = blockIdx.x * PIX_PER_BLK;
    const int b      = n0 >> 12;
    const int hw0    = n0 & 4095;

    // cooperative codebook load (float4)
    {
        const float4* w4 = (const float4*)w;
        float4*       s4 = (float4*)w_s;
        for (int i = tid; i < KC * DD / 4; i += 256) s4[i] = w4[i];
    }
    // x tile -> SMEM [d][p] layout, coalesced float4 over p
    {
        const float* xg = x + (size_t)b * DD * HW + hw0;
        float4* xs4 = (float4*)x_s;
        for (int i = tid; i < DD * (PIX_PER_BLK / 4); i += 256) {
            const int d  = i >> 6;            // / 64 float4s per row
            const int p4 = i & 63;
            xs4[i] = *(const float4*)(xg + (size_t)d * HW + p4 * 4);
        }
    }
    __syncthreads();

    // per-code squared norms (tree)
    for (int k = tid; k < KC; k += 256) {
        float v[DD];
#pragma unroll
        for (int d = 0; d < DD; d++) v[d] = w_s[k * DD + d];
        se2[k] = sumsq_tree64(v);
    }
    // per-pixel squared norm (tree), pixel = tid
    {
        float v[DD];
#pragma unroll
        for (int d = 0; d < DD; d++) v[d] = x_s[d * PIX_PER_BLK + tid];
        xsq[tid] = sumsq_tree64(v);
    }
    __syncthreads();

    float xq[PPT];
#pragma unroll
    for (int p = 0; p < PPT; p++) xq[p] = xsq[pix_t * PPT + p];

    float best[PPT];
    int   bi[PPT];
#pragma unroll
    for (int p = 0; p < PPT; p++) { best[p] = 3.4e38f; bi[p] = 0; }

    for (int kt = 0; kt < KC; kt += KTILE) {
        const int kbase = kt + code_t * CPT;
        float acc[CPT][PPT];
#pragma unroll
        for (int c = 0; c < CPT; c++)
#pragma unroll
            for (int p = 0; p < PPT; p++) acc[c][p] = 0.f;

#pragma unroll 2
        for (int dc = 0; dc < DD; dc += 4) {
            float4 xv0 = *(const float4*)&x_s[(dc + 0) * PIX_PER_BLK + pix_t * PPT];
            float4 xv1 = *(const float4*)&x_s[(dc + 1) * PIX_PER_BLK + pix_t * PPT];
            float4 xv2 = *(const float4*)&x_s[(dc + 2) * PIX_PER_BLK + pix_t * PPT];
            float4 xv3 = *(const float4*)&x_s[(dc + 3) * PIX_PER_BLK + pix_t * PPT];
#pragma unroll
            for (int c = 0; c < CPT; c++) {
                const float4 wv = *(const float4*)&w_s[(kbase + c) * DD + dc];
                // d, d+1, d+2, d+3 accumulated sequentially per chain (bit-exact order)
                acc[c][0] = __fmaf_rn(xv0.x, wv.x, acc[c][0]);
                acc[c][1] = __fmaf_rn(xv0.y, wv.x, acc[c][1]);
                acc[c][2] = __fmaf_rn(xv0.z, wv.x, acc[c][2]);
                acc[c][3] = __fmaf_rn(xv0.w, wv.x, acc[c][3]);
                acc[c][0] = __fmaf_rn(xv1.x, wv.y, acc[c][0]);
                acc[c][1] = __fmaf_rn(xv1.y, wv.y, acc[c][1]);
                acc[c][2] = __fmaf_rn(xv1.z, wv.y, acc[c][2]);
                acc[c][3] = __fmaf_rn(xv1.w, wv.y, acc[c][3]);
                acc[c][0] = __fmaf_rn(xv2.x, wv.z, acc[c][0]);
                acc[c][1] = __fmaf_rn(xv2.y, wv.z, acc[c][1]);
                acc[c][2] = __fmaf_rn(xv2.z, wv.z, acc[c][2]);
                acc[c][3] = __fmaf_rn(xv2.w, wv.z, acc[c][3]);
                acc[c][0] = __fmaf_rn(xv3.x, wv.w, acc[c][0]);
                acc[c][1] = __fmaf_rn(xv3.y, wv.w, acc[c][1]);
                acc[c][2] = __fmaf_rn(xv3.z, wv.w, acc[c][2]);
                acc[c][3] = __fmaf_rn(xv3.w, wv.w, acc[c][3]);
            }
        }
        // epilogue: dist = fl(fl(xsq + wsq) - fl(2*dot)), strict < first-min
#pragma unroll
        for (int c = 0; c < CPT; c++) {
            const int   k   = kbase + c;
            const float wsq = se2[k];
#pragma unroll
            for (int p = 0; p < PPT; p++) {
                const float dist = __fsub_rn(__fadd_rn(xq[p], wsq),
                                             __fadd_rn(acc[c][p], acc[c][p]));
                if (dist < best[p]) { best[p] = dist; bi[p] = k; }
            }
        }
    }

    // cross code-group reduction: lexicographic (dist, idx) min == global first-min
#pragma unroll
    for (int p = 0; p < PPT; p++) {
        redd[code_t * PIX_PER_BLK + pix_t * PPT + p] = best[p];
        redi[code_t * PIX_PER_BLK + pix_t * PPT + p] = bi[p];
    }
    __syncthreads();
    {
        float bd = redd[tid];
        int   bk = redi[tid];
#pragma unroll
        for (int ct = 1; ct < 4; ct++) {
            const float d2 = redd[ct * PIX_PER_BLK + tid];
            const int   k2 = redi[ct * PIX_PER_BLK + tid];
            if (d2 < bd || (d2 == bd && k2 < bk)) { bd = d2; bk = k2; }
        }
        gidx[n0 + tid]    = bk;
        out_idx[n0 + tid] = (float)bk;
    }
}

// ---------------------------------------------------------------------------
// Kernel B: quantized NCHW output (straight-through rounding), one-hot
// scatter, loss accumulation.
// ---------------------------------------------------------------------------
__global__ void __launch_bounds__(256, 1)
vq_scatter(const float* __restrict__ x, const float* __restrict__ w,
           const int* __restrict__ gidx,
           float* __restrict__ out_q, float* __restrict__ out_enc,
           double* __restrict__ losssum)
{
    float* sw = smem;  // [KC * 65] padded
    const int tid = threadIdx.x;

    for (int i = tid; i < KC * DD; i += blockDim.x) {
        const int k = i >> 6;
        const int d = i & 63;
        sw[k * 65 + d] = w[i];
    }
    __syncthreads();

    const int n  = blockIdx.x * blockDim.x + tid;
    const int k  = gidx[n];
    const int b  = n >> 12;
    const int hw = n & 4095;
    const float* xp = x     + (size_t)b * DD * HW + hw;
    float*       qp = out_q + (size_t)b * DD * HW + hw;
    const float* wr = sw + k * 65;

    float s = 0.f;
#pragma unroll
    for (int d = 0; d < DD; d++) {
        const float xv = xp[(size_t)d * HW];
        const float qv = wr[d];
        const float df = __fsub_rn(qv, xv);
        qp[(size_t)d * HW] = __fadd_rn(xv, df);
        s = fmaf(df, df, s);
    }

    out_enc[(size_t)n * KC + k] = 1.0f;

#pragma unroll
    for (int off = 16; off; off >>= 1) s += __shfl_down_sync(0xffffffffu, s, off);
    __shared__ float sred[8];
    if ((tid & 31) == 0) sred[tid >> 5] = s;
    __syncthreads();
    if (tid < 8) {
        float v = sred[tid];
#pragma unroll
        for (int off = 4; off; off >>= 1) v += __shfl_down_sync(0xffu, v, off);
        if (tid == 0) atomicAdd(losssum, (double)v);
    }
}

__global__ void vq_finalize(const double* __restrict__ losssum,
                            float* __restrict__ out_loss)
{
    out_loss[0] = (float)(2.0 * (*losssum) / (double)XNUM);
}

// ---------------------------------------------------------------------------
extern "C" void kernel_launch(void* const* d_in, const int* in_sizes, int n_in,
                              void* d_out, int out_size)
{
    const float* x = (const float*)d_in[0];   // [32, 64, 64, 64] NCHW
    const float* w = (const float*)d_in[1];   // [512, 64]

    float* out      = (float*)d_out;
    float* out_loss = out;
    float* out_q    = out + 1;
    float* out_enc  = out + 1 + (size_t)XNUM;
    float* out_idx  = out + 1 + (size_t)XNUM + (size_t)NPIX * KC;

    int*    gidx_ptr = nullptr;
    double* loss_ptr = nullptr;
    cudaGetSymbolAddress((void**)&gidx_ptr, g_idx);
    cudaGetSymbolAddress((void**)&loss_ptr, g_losssum);

    const int smem_a = (KC * DD + DD * PIX_PER_BLK + KC + PIX_PER_BLK
                        + 4 * PIX_PER_BLK + 4 * PIX_PER_BLK) * (int)sizeof(float);
    const int smem_b = (KC * 65) * (int)sizeof(float);
    cudaFuncSetAttribute(vq_argmin,  cudaFuncAttributeMaxDynamicSharedMemorySize, smem_a);
    cudaFuncSetAttribute(vq_scatter, cudaFuncAttributeMaxDynamicSharedMemorySize, smem_b);

    cudaMemsetAsync(out_enc, 0, (size_t)NPIX * KC * sizeof(float), 0);
    cudaMemsetAsync(loss_ptr, 0, sizeof(double), 0);

    vq_argmin <<<NPIX / PIX_PER_BLK, 256, smem_a>>>(x, w, gidx_ptr, out_idx);
    vq_scatter<<<NPIX / 256, 256, smem_b>>>(x, w, gidx_ptr, out_q, out_enc, loss_ptr);
    vq_finalize<<<1, 1>>>(loss_ptr, out_loss);
}

// round 6
// speedup vs baseline: 1.3523x; 1.1335x over previous
#include <cuda_runtime.h>
#include <cuda_bf16.h>
#include <cstdint>

#define KC   512
#define DD   64
#define HW   4096
#define NB   32
#define NPIX (NB * HW)
#define XNUM (NPIX * DD)

#define PIX_PER_BLK 256
#define PPT 4            // pixels per thread (2 packed pairs)
#define CPT 8            // codes per thread
#define KTILE 32

__device__ int    g_idx[NPIX];
__device__ double g_losssum;

extern __shared__ float smem[];

// ---- packed f32x2 helpers (FFMA2 path; each half is an exact fp32 rn op) ----
__device__ __forceinline__ unsigned long long pack2(float v) {
    unsigned long long r;
    asm("mov.b64 %0, {%1, %1};" : "=l"(r) : "r"(__float_as_uint(v)));
    return r;
}
__device__ __forceinline__ void fma2(unsigned long long& acc,
                                     unsigned long long a, unsigned long long b) {
    asm("fma.rn.f32x2 %0, %1, %2, %3;" : "=l"(acc) : "l"(a), "l"(b), "l"(acc));
}
__device__ __forceinline__ void unpack2(unsigned long long v, float& lo, float& hi) {
    unsigned int l, h;
    asm("mov.b64 {%0, %1}, %2;" : "=r"(l), "=r"(h) : "l"(v));
    lo = __uint_as_float(l);
    hi = __uint_as_float(h);
}

// Reference fp32 reduction tree for 64 elements (vec=2 + shfl butterfly).
__device__ __forceinline__ float sumsq_tree64(const float* v) {
    float p[32];
#pragma unroll
    for (int t = 0; t < 32; t++) {
        float a = __fmul_rn(v[2 * t], v[2 * t]);
        float b = __fmul_rn(v[2 * t + 1], v[2 * t + 1]);
        p[t] = __fadd_rn(a, b);
    }
#pragma unroll
    for (int off = 16; off >= 1; off >>= 1) {
#pragma unroll
        for (int l = 0; l < 16; l++) {
            if (l < off) p[l] = __fadd_rn(p[l], p[l + off]);
        }
    }
    return p[0];
}

// ---------------------------------------------------------------------------
// Kernel A: register-tiled argmin with packed FFMA2 + interleaved enc zeroing
// (alignment-safe: head/tail scalar peel around a guarded float4 body).
// ---------------------------------------------------------------------------
__global__ void __launch_bounds__(256, 1)
vq_argmin(const float* __restrict__ x, const float* __restrict__ w,
          int* __restrict__ gidx, float* __restrict__ out_idx,
          float* __restrict__ out_enc)
{
    float* w_s  = smem;                       // [512*64]
    float* x_s  = w_s + KC * DD;              // [64][256] d-major
    float* se2  = x_s + DD * PIX_PER_BLK;     // [512]
    float* xsq  = se2 + KC;                   // [256]
    float* redd = xsq + PIX_PER_BLK;          // [4*256]
    int*   redi = (int*)(redd + 4 * PIX_PER_BLK); // [4*256]

    const int tid    = threadIdx.x;
    const int pix_t  = tid & 63;
    const int code_t = tid >> 6;
    const int n0     = blockIdx.x * PIX_PER_BLK;
    const int b      = n0 >> 12;
    const int hw0    = n0 & 4095;

    {   // cooperative codebook load
        const float4* w4 = (const float4*)w;
        float4*       s4 = (float4*)w_s;
        for (int i = tid; i < KC * DD / 4; i += 256) s4[i] = w4[i];
    }
    {   // x tile -> SMEM [d][p], coalesced
        const float* xg = x + (size_t)b * DD * HW + hw0;
        float4* xs4 = (float4*)x_s;
        for (int i = tid; i < DD * (PIX_PER_BLK / 4); i += 256) {
            const int d  = i >> 6;
            const int p4 = i & 63;
            xs4[i] = *(const float4*)(xg + (size_t)d * HW + p4 * 4);
        }
    }
    __syncthreads();

    for (int k = tid; k < KC; k += 256) {
        float v[DD];
#pragma unroll
        for (int d = 0; d < DD; d++) v[d] = w_s[k * DD + d];
        se2[k] = sumsq_tree64(v);
    }
    {
        float v[DD];
#pragma unroll
        for (int d = 0; d < DD; d++) v[d] = x_s[d * PIX_PER_BLK + tid];
        xsq[tid] = sumsq_tree64(v);
    }
    __syncthreads();

    float xq[PPT];
#pragma unroll
    for (int p = 0; p < PPT; p++) xq[p] = xsq[pix_t * PPT + p];

    float best[PPT];
    int   bi[PPT];
#pragma unroll
    for (int p = 0; p < PPT; p++) { best[p] = 3.4e38f; bi[p] = 0; }

    // enc zero-fill: this block owns rows n0..n0+255 (131072 floats), but the
    // region base is only 4B-aligned (d_out + 1 + XNUM). Peel to 16B alignment.
    float*   encbase = out_enc + (size_t)n0 * KC;
    const unsigned misal = (unsigned)((unsigned long long)(uintptr_t)encbase & 15ull);
    const int head   = (int)(((16u - misal) & 15u) >> 2);
    float4*  ez      = (float4*)(encbase + head);
    const int body4  = (PIX_PER_BLK * KC - head) >> 2;  // # of float4 stores
    const int tail   = (PIX_PER_BLK * KC - head) & 3;
    const float4 zero4 = make_float4(0.f, 0.f, 0.f, 0.f);

    if (tid == 0) {
        for (int i = 0; i < head; i++) encbase[i] = 0.f;
        for (int i = 0; i < tail; i++) encbase[head + body4 * 4 + i] = 0.f;
    }

    for (int kt = 0; kt < KC; kt += KTILE) {
        {   // interleave up to 8 coalesced enc-zero stores per thread per k-tile
            const int it = kt >> 5;   // 0..15
#pragma unroll
            for (int j = 0; j < 8; j++) {
                const int idx = (it * 8 + j) * 256 + tid;
                if (idx < body4) ez[idx] = zero4;
            }
        }

        const int kbase = kt + code_t * CPT;
        unsigned long long a01[CPT], a23[CPT];
#pragma unroll
        for (int c = 0; c < CPT; c++) { a01[c] = 0ull; a23[c] = 0ull; }

#pragma unroll 2
        for (int dc = 0; dc < DD; dc += 4) {
            // each ulonglong2: .x = (p0,p1) packed, .y = (p2,p3) packed
            const ulonglong2 xv0 = *(const ulonglong2*)&x_s[(dc + 0) * PIX_PER_BLK + pix_t * PPT];
            const ulonglong2 xv1 = *(const ulonglong2*)&x_s[(dc + 1) * PIX_PER_BLK + pix_t * PPT];
            const ulonglong2 xv2 = *(const ulonglong2*)&x_s[(dc + 2) * PIX_PER_BLK + pix_t * PPT];
            const ulonglong2 xv3 = *(const ulonglong2*)&x_s[(dc + 3) * PIX_PER_BLK + pix_t * PPT];
#pragma unroll
            for (int c = 0; c < CPT; c++) {
                const float4 wv = *(const float4*)&w_s[(kbase + c) * DD + dc];
                const unsigned long long w0 = pack2(wv.x);
                const unsigned long long w1 = pack2(wv.y);
                const unsigned long long w2 = pack2(wv.z);
                const unsigned long long w3 = pack2(wv.w);
                // sequential in d per (pixel, code) chain -> bit-exact order
                fma2(a01[c], xv0.x, w0); fma2(a23[c], xv0.y, w0);
                fma2(a01[c], xv1.x, w1); fma2(a23[c], xv1.y, w1);
                fma2(a01[c], xv2.x, w2); fma2(a23[c], xv2.y, w2);
                fma2(a01[c], xv3.x, w3); fma2(a23[c], xv3.y, w3);
            }
        }
#pragma unroll
        for (int c = 0; c < CPT; c++) {
            const int   k   = kbase + c;
            const float wsq = se2[k];
            float d0, d1, d2, d3;
            unpack2(a01[c], d0, d1);
            unpack2(a23[c], d2, d3);
            const float t0 = __fsub_rn(__fadd_rn(xq[0], wsq), __fadd_rn(d0, d0));
            const float t1 = __fsub_rn(__fadd_rn(xq[1], wsq), __fadd_rn(d1, d1));
            const float t2 = __fsub_rn(__fadd_rn(xq[2], wsq), __fadd_rn(d2, d2));
            const float t3 = __fsub_rn(__fadd_rn(xq[3], wsq), __fadd_rn(d3, d3));
            if (t0 < best[0]) { best[0] = t0; bi[0] = k; }
            if (t1 < best[1]) { best[1] = t1; bi[1] = k; }
            if (t2 < best[2]) { best[2] = t2; bi[2] = k; }
            if (t3 < best[3]) { best[3] = t3; bi[3] = k; }
        }
    }

#pragma unroll
    for (int p = 0; p < PPT; p++) {
        redd[code_t * PIX_PER_BLK + pix_t * PPT + p] = best[p];
        redi[code_t * PIX_PER_BLK + pix_t * PPT + p] = bi[p];
    }
    __syncthreads();
    {
        float bd = redd[tid];
        int   bk = redi[tid];
#pragma unroll
        for (int ct = 1; ct < 4; ct++) {
            const float d2 = redd[ct * PIX_PER_BLK + tid];
            const int   k2 = redi[ct * PIX_PER_BLK + tid];
            if (d2 < bd || (d2 == bd && k2 < bk)) { bd = d2; bk = k2; }
        }
        gidx[n0 + tid]    = bk;
        out_idx[n0 + tid] = (float)bk;
    }
}

// ---------------------------------------------------------------------------
// Kernel B: quantized NCHW output (straight-through rounding), one-hot
// set (enc already zeroed by kernel A), loss accumulation.
// ---------------------------------------------------------------------------
__global__ void __launch_bounds__(256, 1)
vq_scatter(const float* __restrict__ x, const float* __restrict__ w,
           const int* __restrict__ gidx,
           float* __restrict__ out_q, float* __restrict__ out_enc,
           double* __restrict__ losssum)
{
    float* sw = smem;  // [KC * 65] padded
    const int tid = threadIdx.x;

    for (int i = tid; i < KC * DD; i += blockDim.x) {
        const int k = i >> 6;
        const int d = i & 63;
        sw[k * 65 + d] = w[i];
    }
    __syncthreads();

    const int n  = blockIdx.x * blockDim.x + tid;
    const int k  = gidx[n];
    const int b  = n >> 12;
    const int hw = n & 4095;
    const float* xp = x     + (size_t)b * DD * HW + hw;
    float*       qp = out_q + (size_t)b * DD * HW + hw;
    const float* wr = sw + k * 65;

    float s = 0.f;
#pragma unroll
    for (int d = 0; d < DD; d++) {
        const float xv = xp[(size_t)d * HW];
        const float qv = wr[d];
        const float df = __fsub_rn(qv, xv);
        qp[(size_t)d * HW] = __fadd_rn(xv, df);
        s = fmaf(df, df, s);
    }

    out_enc[(size_t)n * KC + k] = 1.0f;

#pragma unroll
    for (int off = 16; off; off >>= 1) s += __shfl_down_sync(0xffffffffu, s, off);
    __shared__ float sred[8];
    if ((tid & 31) == 0) sred[tid >> 5] = s;
    __syncthreads();
    if (tid < 8) {
        float v = sred[tid];
#pragma unroll
        for (int off = 4; off; off >>= 1) v += __shfl_down_sync(0xffu, v, off);
        if (tid == 0) atomicAdd(losssum, (double)v);
    }
}

__global__ void vq_finalize(const double* __restrict__ losssum,
                            float* __restrict__ out_loss)
{
    out_loss[0] = (float)(2.0 * (*losssum) / (double)XNUM);
}

// ---------------------------------------------------------------------------
extern "C" void kernel_launch(void* const* d_in, const int* in_sizes, int n_in,
                              void* d_out, int out_size)
{
    const float* x = (const float*)d_in[0];   // [32, 64, 64, 64] NCHW
    const float* w = (const float*)d_in[1];   // [512, 64]

    float* out      = (float*)d_out;
    float* out_loss = out;
    float* out_q    = out + 1;
    float* out_enc  = out + 1 + (size_t)XNUM;
    float* out_idx  = out + 1 + (size_t)XNUM + (size_t)NPIX * KC;

    int*    gidx_ptr = nullptr;
    double* loss_ptr = nullptr;
    cudaGetSymbolAddress((void**)&gidx_ptr, g_idx);
    cudaGetSymbolAddress((void**)&loss_ptr, g_losssum);

    const int smem_a = (KC * DD + DD * PIX_PER_BLK + KC + PIX_PER_BLK
                        + 4 * PIX_PER_BLK + 4 * PIX_PER_BLK) * (int)sizeof(float);
    const int smem_b = (KC * 65) * (int)sizeof(float);
    cudaFuncSetAttribute(vq_argmin,  cudaFuncAttributeMaxDynamicSharedMemorySize, smem_a);
    cudaFuncSetAttribute(vq_scatter, cudaFuncAttributeMaxDynamicSharedMemorySize, smem_b);

    cudaMemsetAsync(loss_ptr, 0, sizeof(double), 0);

    vq_argmin <<<NPIX / PIX_PER_BLK, 256, smem_a>>>(x, w, gidx_ptr, out_idx, out_enc);
    vq_scatter<<<NPIX / 256, 256, smem_b>>>(x, w, gidx_ptr, out_q, out_enc, loss_ptr);
    vq_finalize<<<1, 1>>>(loss_ptr, out_loss);
}

// round 8
// speedup vs baseline: 1.3924x; 1.0296x over previous
#include <cuda_runtime.h>
#include <cuda_bf16.h>
#include <cstdint>

#define KC   512
#define DD   64
#define HW   4096
#define NB   32
#define NPIX (NB * HW)
#define XNUM (NPIX * DD)

#define TILE_M  128
#define NTILES  (NPIX / TILE_M)   // 1024

__device__ int    g_idx[NPIX];
__device__ double g_losssum;
__device__ float  g_wsq[KC];
__device__ int    g_flag[NPIX];
__device__ int    g_nflag;

// smem byte map for the MMA filter kernel (stride-68 padded tiles)
#define XS_OFF   0
#define WS_OFF   (XS_OFF + 128 * 68 * 4)    // 34816
#define WSQ_OFF  (WS_OFF + 512 * 68 * 4)    // 174080
#define S1_OFF   (WSQ_OFF + 512 * 4)        // 176128
#define SM_TOT   (S1_OFF + 256 * 4)         // 177152

__device__ __forceinline__ uint32_t to_tf32(float v) {
    uint32_t t;
    asm("cvt.rna.tf32.f32 %0, %1;" : "=r"(t) : "f"(v));
    return t;
}
__device__ __forceinline__ void mma_tf32(float& c0, float& c1, float& c2, float& c3,
                                         uint32_t a0, uint32_t a1, uint32_t a2, uint32_t a3,
                                         uint32_t b0, uint32_t b1) {
    asm volatile(
        "mma.sync.aligned.m16n8k8.row.col.f32.tf32.tf32.f32 "
        "{%0,%1,%2,%3}, {%4,%5,%6,%7}, {%8,%9}, {%0,%1,%2,%3};"
        : "+f"(c0), "+f"(c1), "+f"(c2), "+f"(c3)
        : "r"(a0), "r"(a1), "r"(a2), "r"(a3), "r"(b0), "r"(b1));
}

// Reference fp32 reduction tree for 64 elements (vec=2 + butterfly).
__device__ __forceinline__ float sumsq_tree64(const float* v) {
    float p[32];
#pragma unroll
    for (int t = 0; t < 32; t++) {
        float a = __fmul_rn(v[2 * t], v[2 * t]);
        float b = __fmul_rn(v[2 * t + 1], v[2 * t + 1]);
        p[t] = __fadd_rn(a, b);
    }
#pragma unroll
    for (int off = 16; off >= 1; off >>= 1)
#pragma unroll
        for (int l = 0; l < 16; l++)
            if (l < off) p[l] = __fadd_rn(p[l], p[l + off]);
    return p[0];
}

// ---------------------------------------------------------------------------
// K1: per-code squared norms (bit-exact tree) + flag counter reset
// ---------------------------------------------------------------------------
__global__ void vq_prep(const float* __restrict__ w)
{
    const int k = threadIdx.x;
    if (k < KC) {
        float v[DD];
#pragma unroll
        for (int d = 0; d < DD; d++) v[d] = w[k * DD + d];
        g_wsq[k] = sumsq_tree64(v);
    }
    if (k == 0) g_nflag = 0;
}

// ---------------------------------------------------------------------------
// K2: tf32 mma.sync filter + fused enc zero-fill.
// Block = 256 thr = 8 warps; warp handles 16 pixels x 512 codes.
// ---------------------------------------------------------------------------
__global__ void __launch_bounds__(256, 1)
vq_mma_filter(const float* __restrict__ x, const float* __restrict__ w,
              int* __restrict__ gidx, float* __restrict__ out_idx,
              float* __restrict__ out_enc)
{
    extern __shared__ char smc[];
    uint32_t* x_s   = (uint32_t*)(smc + XS_OFF);   // [128][68] tf32
    uint32_t* w_s   = (uint32_t*)(smc + WS_OFF);   // [512][68] tf32
    float*    wsq_s = (float*)(smc + WSQ_OFF);     // [512]
    float*    s1h   = (float*)(smc + S1_OFF);      // [256]

    const int tid = threadIdx.x;
    const int n0  = blockIdx.x * TILE_M;
    const int b   = n0 >> 12;
    const int hw0 = n0 & 4095;

    // ---- codebook -> tf32 SMEM (padded stride 68) + wsq
    for (int i = tid; i < KC * DD; i += 256) {
        const int k = i >> 6, d = i & 63;
        w_s[k * 68 + d] = to_tf32(w[i]);
    }
    for (int i = tid; i < KC; i += 256) wsq_s[i] = g_wsq[i];

    // ---- x tile -> tf32 SMEM [p][d] stride 68; per-pixel L1-norm halves
    {
        const float* xg = x + (size_t)b * DD * HW + hw0;
        const int p = tid & 127;
        float s1 = 0.f;
#pragma unroll 8
        for (int j = 0; j < 32; j++) {
            const int d = (tid >> 7) + 2 * j;
            const float v = xg[(size_t)d * HW + p];
            s1 += fabsf(v);
            x_s[p * 68 + d] = to_tf32(v);
        }
        s1h[tid] = s1;
    }

    // ---- fused enc zero-fill for rows n0..n0+127 (aligned-peeled float4)
    {
        float* encb = out_enc + (size_t)n0 * KC;
        const unsigned mis = (unsigned)((unsigned long long)(uintptr_t)encb & 15ull);
        const int head  = (int)(((16u - mis) & 15u) >> 2);
        float4*  ez     = (float4*)(encb + head);
        const int body4 = (TILE_M * KC - head) >> 2;
        const int tail  = (TILE_M * KC - head) & 3;
        if (tid == 0) {
            for (int i = 0; i < head; i++) encb[i] = 0.f;
            for (int i = 0; i < tail; i++) encb[head + body4 * 4 + i] = 0.f;
        }
        const float4 z4 = make_float4(0.f, 0.f, 0.f, 0.f);
        for (int i = tid; i < body4; i += 256) ez[i] = z4;
    }
    __syncthreads();

    // ---- per-warp MMA: 16 pixels x 512 codes
    const int lane = tid & 31, wid = tid >> 5;
    const int gid  = lane >> 2, tI = lane & 3;
    const int r0   = wid * 16 + gid, r1 = r0 + 8;

    uint32_t A0[8], A1[8], A2[8], A3[8];
#pragma unroll
    for (int k = 0; k < 8; k++) {
        A0[k] = x_s[r0 * 68 + 8 * k + tI];
        A1[k] = x_s[r1 * 68 + 8 * k + tI];
        A2[k] = x_s[r0 * 68 + 8 * k + tI + 4];
        A3[k] = x_s[r1 * 68 + 8 * k + tI + 4];
    }

    float best0 = 3.4e38f, sec0 = 3.4e38f, best1 = 3.4e38f, sec1 = 3.4e38f;
    int   bi0 = 0, bi1 = 0;

#pragma unroll 1
    for (int nt = 0; nt < 64; nt += 4) {
        float c[4][4];
#pragma unroll
        for (int q = 0; q < 4; q++)
#pragma unroll
            for (int f = 0; f < 4; f++) c[q][f] = 0.f;

#pragma unroll
        for (int k = 0; k < 8; k++) {
#pragma unroll
            for (int q = 0; q < 4; q++) {
                const int row = (nt + q) * 8 + gid;
                const uint32_t b0 = w_s[row * 68 + 8 * k + tI];
                const uint32_t b1 = w_s[row * 68 + 8 * k + tI + 4];
                mma_tf32(c[q][0], c[q][1], c[q][2], c[q][3],
                         A0[k], A1[k], A2[k], A3[k], b0, b1);
            }
        }
#pragma unroll
        for (int q = 0; q < 4; q++) {
            const int cb = (nt + q) * 8 + 2 * tI;
            const float w0 = wsq_s[cb], w1 = wsq_s[cb + 1];
            const float d00 = __fmaf_rn(-2.f, c[q][0], w0);  // pixel r0, code cb
            const float d01 = __fmaf_rn(-2.f, c[q][1], w1);  // pixel r0, code cb+1
            const float d10 = __fmaf_rn(-2.f, c[q][2], w0);  // pixel r1, code cb
            const float d11 = __fmaf_rn(-2.f, c[q][3], w1);
            // increasing-code order per thread -> strict < keeps first min
            if (d00 < best0) { sec0 = best0; best0 = d00; bi0 = cb; }
            else if (d00 < sec0) sec0 = d00;
            if (d01 < best0) { sec0 = best0; best0 = d01; bi0 = cb + 1; }
            else if (d01 < sec0) sec0 = d01;
            if (d10 < best1) { sec1 = best1; best1 = d10; bi1 = cb; }
            else if (d10 < sec1) sec1 = d10;
            if (d11 < best1) { sec1 = best1; best1 = d11; bi1 = cb + 1; }
            else if (d11 < sec1) sec1 = d11;
        }
    }

    // merge top-2 across the 4 threads of each quad (butterfly xor 1, 2)
#pragma unroll
    for (int m = 1; m <= 2; m <<= 1) {
        float ob = __shfl_xor_sync(0xffffffffu, best0, m);
        float os = __shfl_xor_sync(0xffffffffu, sec0,  m);
        int  obi = __shfl_xor_sync(0xffffffffu, bi0,   m);
        if (ob < best0 || (ob == best0 && obi < bi0)) { sec0 = fminf(best0, os); best0 = ob; bi0 = obi; }
        else sec0 = fminf(sec0, ob);
        ob  = __shfl_xor_sync(0xffffffffu, best1, m);
        os  = __shfl_xor_sync(0xffffffffu, sec1,  m);
        obi = __shfl_xor_sync(0xffffffffu, bi1,   m);
        if (ob < best1 || (ob == best1 && obi < bi1)) { sec1 = fminf(best1, os); best1 = ob; bi1 = obi; }
        else sec1 = fminf(sec1, ob);
    }

    if (tI == 0) {
        const float S1a = s1h[r0] + s1h[r0 + 128];
        const float S1b = s1h[r1] + s1h[r1 + 128];
        gidx[n0 + r0]    = bi0;
        out_idx[n0 + r0] = (float)bi0;
        gidx[n0 + r1]    = bi1;
        out_idx[n0 + r1] = (float)bi1;
        if (__fsub_rn(sec0, best0) < __fmaf_rn(1e-5f, S1a, 4e-5f)) {
            const int pos = atomicAdd(&g_nflag, 1);
            g_flag[pos] = n0 + r0;
        }
        if (__fsub_rn(sec1, best1) < __fmaf_rn(1e-5f, S1b, 4e-5f)) {
            const int pos = atomicAdd(&g_nflag, 1);
            g_flag[pos] = n0 + r1;
        }
    }
}

// ---------------------------------------------------------------------------
// K3: bit-exact fallback for flagged pixels (1 warp per pixel).
// ---------------------------------------------------------------------------
__global__ void __launch_bounds__(256, 1)
vq_fallback(const float* __restrict__ x, const float* __restrict__ w,
            int* __restrict__ gidx, float* __restrict__ out_idx)
{
    if (blockIdx.x * 8 >= g_nflag) return;
    extern __shared__ char smc[];
    float* w_s   = (float*)smc;                          // [512*65] padded
    float* wsq_s = (float*)(smc + KC * 65 * 4);          // [512]
    float* xrow  = (float*)(smc + KC * 65 * 4 + KC * 4); // [8][64]
    const int tid = threadIdx.x, wid = tid >> 5, lane = tid & 31;

    for (int i = tid; i < KC * DD; i += 256) {
        const int k = i >> 6, d = i & 63;
        w_s[k * 65 + d] = w[i];
    }
    for (int i = tid; i < KC; i += 256) wsq_s[i] = g_wsq[i];
    __syncthreads();

    const int nflag = g_nflag;
    for (int f = blockIdx.x * 8 + wid; f < nflag; f += gridDim.x * 8) {
        const int n  = g_flag[f];
        const int b  = n >> 12, hw = n & 4095;
        const float* xp = x + (size_t)b * DD * HW + hw;
        xrow[wid * 64 + lane]      = xp[(size_t)lane * HW];
        xrow[wid * 64 + lane + 32] = xp[(size_t)(lane + 32) * HW];
        __syncwarp();
        float pa = __fmul_rn(xrow[wid * 64 + 2 * lane],     xrow[wid * 64 + 2 * lane]);
        float pb = __fmul_rn(xrow[wid * 64 + 2 * lane + 1], xrow[wid * 64 + 2 * lane + 1]);
        float pt = __fadd_rn(pa, pb);
#pragma unroll
        for (int off = 16; off >= 1; off >>= 1) {
            const float q = __shfl_down_sync(0xffffffffu, pt, off);
            pt = __fadd_rn(pt, q);
        }
        const float xsq = __shfl_sync(0xffffffffu, pt, 0);

        float bd = 3.4e38f; int bk = 0;
#pragma unroll 1
        for (int j = 0; j < 16; j++) {
            const int k = lane + 32 * j;
            float dot = 0.f;
#pragma unroll
            for (int d = 0; d < DD; d++)
                dot = __fmaf_rn(xrow[wid * 64 + d], w_s[k * 65 + d], dot);
            const float dist = __fsub_rn(__fadd_rn(xsq, wsq_s[k]), __fadd_rn(dot, dot));
            if (dist < bd) { bd = dist; bk = k; }
        }
#pragma unroll
        for (int off = 16; off >= 1; off >>= 1) {
            const float od = __shfl_down_sync(0xffffffffu, bd, off);
            const int   ok = __shfl_down_sync(0xffffffffu, bk, off);
            if (od < bd || (od == bd && ok < bk)) { bd = od; bk = ok; }
        }
        if (lane == 0) { gidx[n] = bk; out_idx[n] = (float)bk; }
        __syncwarp();
    }
}

// ---------------------------------------------------------------------------
// K4: quantized NCHW output (straight-through rounding), one-hot set, loss.
// ---------------------------------------------------------------------------
__global__ void __launch_bounds__(256, 1)
vq_scatter(const float* __restrict__ x, const float* __restrict__ w,
           const int* __restrict__ gidx,
           float* __restrict__ out_q, float* __restrict__ out_enc,
           double* __restrict__ losssum)
{
    extern __shared__ char smc[];
    float* sw = (float*)smc;  // [KC * 65] padded
    const int tid = threadIdx.x;

    for (int i = tid; i < KC * DD; i += blockDim.x) {
        const int k = i >> 6, d = i & 63;
        sw[k * 65 + d] = w[i];
    }
    __syncthreads();

    const int n  = blockIdx.x * blockDim.x + tid;
    const int k  = gidx[n];
    const int b  = n >> 12, hw = n & 4095;
    const float* xp = x     + (size_t)b * DD * HW + hw;
    float*       qp = out_q + (size_t)b * DD * HW + hw;
    const float* wr = sw + k * 65;

    float s = 0.f;
#pragma unroll
    for (int d = 0; d < DD; d++) {
        const float xv = xp[(size_t)d * HW];
        const float qv = wr[d];
        const float df = __fsub_rn(qv, xv);
        qp[(size_t)d * HW] = __fadd_rn(xv, df);
        s = fmaf(df, df, s);
    }
    out_enc[(size_t)n * KC + k] = 1.0f;

#pragma unroll
    for (int off = 16; off; off >>= 1) s += __shfl_down_sync(0xffffffffu, s, off);
    __shared__ float sred[8];
    if ((tid & 31) == 0) sred[tid >> 5] = s;
    __syncthreads();
    if (tid < 8) {
        float v = sred[tid];
#pragma unroll
        for (int off = 4; off; off >>= 1) v += __shfl_down_sync(0xffu, v, off);
        if (tid == 0) atomicAdd(losssum, (double)v);
    }
}

__global__ void vq_finalize(const double* __restrict__ losssum,
                            float* __restrict__ out_loss)
{
    out_loss[0] = (float)(2.0 * (*losssum) / (double)XNUM);
}

// ---------------------------------------------------------------------------
extern "C" void kernel_launch(void* const* d_in, const int* in_sizes, int n_in,
                              void* d_out, int out_size)
{
    const float* x = (const float*)d_in[0];   // [32, 64, 64, 64] NCHW
    const float* w = (const float*)d_in[1];   // [512, 64]

    float* out      = (float*)d_out;
    float* out_loss = out;
    float* out_q    = out + 1;
    float* out_enc  = out + 1 + (size_t)XNUM;
    float* out_idx  = out + 1 + (size_t)XNUM + (size_t)NPIX * KC;

    int*    gidx_ptr = nullptr;
    double* loss_ptr = nullptr;
    cudaGetSymbolAddress((void**)&gidx_ptr, g_idx);
    cudaGetSymbolAddress((void**)&loss_ptr, g_losssum);

    const int smem_fb = KC * 65 * 4 + KC * 4 + 8 * DD * 4;
    const int smem_sc = KC * 65 * 4;
    cudaFuncSetAttribute(vq_mma_filter, cudaFuncAttributeMaxDynamicSharedMemorySize, SM_TOT);
    cudaFuncSetAttribute(vq_fallback,   cudaFuncAttributeMaxDynamicSharedMemorySize, smem_fb);
    cudaFuncSetAttribute(vq_scatter,    cudaFuncAttributeMaxDynamicSharedMemorySize, smem_sc);

    cudaMemsetAsync(loss_ptr, 0, sizeof(double), 0);

    vq_prep      <<<1, 512>>>(w);
    vq_mma_filter<<<NTILES, 256, SM_TOT>>>(x, w, gidx_ptr, out_idx, out_enc);
    vq_fallback  <<<128, 256, smem_fb>>>(x, w, gidx_ptr, out_idx);
    vq_scatter   <<<NPIX / 256, 256, smem_sc>>>(x, w, gidx_ptr, out_q, out_enc, loss_ptr);
    vq_finalize  <<<1, 1>>>(loss_ptr, out_loss);
}

// round 9
// speedup vs baseline: 1.5692x; 1.1270x over previous
#include <cuda_runtime.h>
#include <cuda_fp16.h>
#include <cstdint>

#define KC   512
#define DD   64
#define HW   4096
#define NB   32
#define NPIX (NB * HW)
#define XNUM (NPIX * DD)

#define TILE_M  128
#define NTILES  (NPIX / TILE_M)   // 1024

__device__ int    g_idx[NPIX];
__device__ double g_losssum;
__device__ float  g_wsq[KC];
__device__ int    g_flag[NPIX];
__device__ int    g_nflag;

// smem word map for the fp16 MMA filter (stride-36 padded half2 tiles)
#define XS_OFF   0
#define WS_OFF   (XS_OFF + 128 * 36 * 4)     // 18432 B
#define WSQ_OFF  (WS_OFF + 512 * 36 * 4)     // 92160 B
#define S1_OFF   (WSQ_OFF + 512 * 4)         // 94208 B
#define SM_TOT   (S1_OFF + 256 * 4)          // 95232 B

__device__ __forceinline__ void mma_f16(float& c0, float& c1, float& c2, float& c3,
                                        uint32_t a0, uint32_t a1, uint32_t a2, uint32_t a3,
                                        uint32_t b0, uint32_t b1) {
    asm volatile(
        "mma.sync.aligned.m16n8k16.row.col.f32.f16.f16.f32 "
        "{%0,%1,%2,%3}, {%4,%5,%6,%7}, {%8,%9}, {%0,%1,%2,%3};"
        : "+f"(c0), "+f"(c1), "+f"(c2), "+f"(c3)
        : "r"(a0), "r"(a1), "r"(a2), "r"(a3), "r"(b0), "r"(b1));
}
__device__ __forceinline__ uint32_t packh2(float lo, float hi) {
    const __half2 h = __floats2half2_rn(lo, hi);
    return *(const uint32_t*)&h;
}

// Reference fp32 reduction tree for 64 elements (vec=2 + butterfly).
__device__ __forceinline__ float sumsq_tree64(const float* v) {
    float p[32];
#pragma unroll
    for (int t = 0; t < 32; t++) {
        float a = __fmul_rn(v[2 * t], v[2 * t]);
        float b = __fmul_rn(v[2 * t + 1], v[2 * t + 1]);
        p[t] = __fadd_rn(a, b);
    }
#pragma unroll
    for (int off = 16; off >= 1; off >>= 1)
#pragma unroll
        for (int l = 0; l < 16; l++)
            if (l < off) p[l] = __fadd_rn(p[l], p[l + off]);
    return p[0];
}

// ---------------------------------------------------------------------------
// K1: per-code squared norms (bit-exact tree) + flag counter reset
// ---------------------------------------------------------------------------
__global__ void vq_prep(const float* __restrict__ w)
{
    const int k = threadIdx.x;
    if (k < KC) {
        float v[DD];
#pragma unroll
        for (int d = 0; d < DD; d++) v[d] = w[k * DD + d];
        g_wsq[k] = sumsq_tree64(v);
    }
    if (k == 0) g_nflag = 0;
}

// ---------------------------------------------------------------------------
// K2: fp16 m16n8k16 mma.sync filter + fused enc zero-fill.
// Block = 256 thr = 8 warps; warp handles 16 pixels x 512 codes.
// ---------------------------------------------------------------------------
__global__ void __launch_bounds__(256, 2)
vq_mma_filter(const float* __restrict__ x, const float* __restrict__ w,
              int* __restrict__ gidx, float* __restrict__ out_idx,
              float* __restrict__ out_enc)
{
    extern __shared__ char smc[];
    uint32_t* x_s   = (uint32_t*)(smc + XS_OFF);   // [128][36] half2 words
    uint32_t* w_s   = (uint32_t*)(smc + WS_OFF);   // [512][36] half2 words
    float*    wsq_s = (float*)(smc + WSQ_OFF);     // [512]
    float*    s1h   = (float*)(smc + S1_OFF);      // [256]

    const int tid = threadIdx.x;
    const int n0  = blockIdx.x * TILE_M;
    const int b   = n0 >> 12;
    const int hw0 = n0 & 4095;

    // ---- codebook -> packed fp16 SMEM (row stride 36 words) + wsq
    for (int i = tid; i < KC * 32; i += 256) {
        const int k = i >> 5, j = i & 31;
        const float2 v = *(const float2*)(w + k * DD + 2 * j);
        w_s[k * 36 + j] = packh2(v.x, v.y);
    }
    for (int i = tid; i < KC; i += 256) wsq_s[i] = g_wsq[i];

    // ---- x tile -> packed fp16 SMEM [p][d/2]; per-pixel L1-norm halves
    {
        const float* xg = x + (size_t)b * DD * HW + hw0;
        const int p = tid & 127, h = tid >> 7;   // h selects d-half [32h,32h+32)
        float s1 = 0.f;
#pragma unroll 4
        for (int j = 0; j < 16; j++) {
            const int d = 32 * h + 2 * j;
            const float v0 = xg[(size_t)d * HW + p];
            const float v1 = xg[(size_t)(d + 1) * HW + p];
            s1 += fabsf(v0) + fabsf(v1);
            x_s[p * 36 + 16 * h + j] = packh2(v0, v1);
        }
        s1h[tid] = s1;
    }

    // ---- fused enc zero-fill for rows n0..n0+127 (aligned-peeled float4)
    {
        float* encb = out_enc + (size_t)n0 * KC;
        const unsigned mis = (unsigned)((unsigned long long)(uintptr_t)encb & 15ull);
        const int head  = (int)(((16u - mis) & 15u) >> 2);
        float4*  ez     = (float4*)(encb + head);
        const int body4 = (TILE_M * KC - head) >> 2;
        const int tail  = (TILE_M * KC - head) & 3;
        if (tid == 0) {
            for (int i = 0; i < head; i++) encb[i] = 0.f;
            for (int i = 0; i < tail; i++) encb[head + body4 * 4 + i] = 0.f;
        }
        const float4 z4 = make_float4(0.f, 0.f, 0.f, 0.f);
        for (int i = tid; i < body4; i += 256) ez[i] = z4;
    }
    __syncthreads();

    // ---- per-warp MMA: 16 pixels x 512 codes, K=64 via 4 k-steps of 16
    const int lane = tid & 31, wid = tid >> 5;
    const int gid  = lane >> 2, tI = lane & 3;
    const int r0   = wid * 16 + gid, r1 = r0 + 8;

    // A fragments: a[kk][0..3]; rows r0/r1, k-words tI / tI+4 (+8 per kk)
    uint32_t A[4][4];
#pragma unroll
    for (int kk = 0; kk < 4; kk++) {
        A[kk][0] = x_s[r0 * 36 + 8 * kk + tI];
        A[kk][1] = x_s[r1 * 36 + 8 * kk + tI];
        A[kk][2] = x_s[r0 * 36 + 8 * kk + tI + 4];
        A[kk][3] = x_s[r1 * 36 + 8 * kk + tI + 4];
    }

    float best0 = 3.4e38f, sec0 = 3.4e38f, best1 = 3.4e38f, sec1 = 3.4e38f;
    int   bi0 = 0, bi1 = 0;

#pragma unroll 1
    for (int nt = 0; nt < 64; nt += 4) {
        float c[4][4];
#pragma unroll
        for (int q = 0; q < 4; q++)
#pragma unroll
            for (int f = 0; f < 4; f++) c[q][f] = 0.f;

#pragma unroll
        for (int kk = 0; kk < 4; kk++) {
#pragma unroll
            for (int q = 0; q < 4; q++) {
                const int row = (nt + q) * 8 + gid;       // code row for B frag
                const uint32_t b0 = w_s[row * 36 + 8 * kk + tI];
                const uint32_t b1 = w_s[row * 36 + 8 * kk + tI + 4];
                mma_f16(c[q][0], c[q][1], c[q][2], c[q][3],
                        A[kk][0], A[kk][1], A[kk][2], A[kk][3], b0, b1);
            }
        }
#pragma unroll
        for (int q = 0; q < 4; q++) {
            const int cb = (nt + q) * 8 + 2 * tI;
            const float w0 = wsq_s[cb], w1 = wsq_s[cb + 1];
            const float d00 = __fmaf_rn(-2.f, c[q][0], w0);
            const float d01 = __fmaf_rn(-2.f, c[q][1], w1);
            const float d10 = __fmaf_rn(-2.f, c[q][2], w0);
            const float d11 = __fmaf_rn(-2.f, c[q][3], w1);
            if (d00 < best0) { sec0 = best0; best0 = d00; bi0 = cb; }
            else if (d00 < sec0) sec0 = d00;
            if (d01 < best0) { sec0 = best0; best0 = d01; bi0 = cb + 1; }
            else if (d01 < sec0) sec0 = d01;
            if (d10 < best1) { sec1 = best1; best1 = d10; bi1 = cb; }
            else if (d10 < sec1) sec1 = d10;
            if (d11 < best1) { sec1 = best1; best1 = d11; bi1 = cb + 1; }
            else if (d11 < sec1) sec1 = d11;
        }
    }

    // merge top-2 across the 4 threads of each quad (butterfly xor 1, 2)
#pragma unroll
    for (int m = 1; m <= 2; m <<= 1) {
        float ob = __shfl_xor_sync(0xffffffffu, best0, m);
        float os = __shfl_xor_sync(0xffffffffu, sec0,  m);
        int  obi = __shfl_xor_sync(0xffffffffu, bi0,   m);
        if (ob < best0 || (ob == best0 && obi < bi0)) { sec0 = fminf(best0, os); best0 = ob; bi0 = obi; }
        else sec0 = fminf(sec0, ob);
        ob  = __shfl_xor_sync(0xffffffffu, best1, m);
        os  = __shfl_xor_sync(0xffffffffu, sec1,  m);
        obi = __shfl_xor_sync(0xffffffffu, bi1,   m);
        if (ob < best1 || (ob == best1 && obi < bi1)) { sec1 = fminf(best1, os); best1 = ob; bi1 = obi; }
        else sec1 = fminf(sec1, ob);
    }

    if (tI == 0) {
        const float S1a = s1h[r0] + s1h[r0 + 128];
        const float S1b = s1h[r1] + s1h[r1 + 128];
        gidx[n0 + r0]    = bi0;
        out_idx[n0 + r0] = (float)bi0;
        gidx[n0 + r1]    = bi1;
        out_idx[n0 + r1] = (float)bi1;
        if (__fsub_rn(sec0, best0) < __fmaf_rn(1e-5f, S1a, 4e-5f)) {
            const int pos = atomicAdd(&g_nflag, 1);
            g_flag[pos] = n0 + r0;
        }
        if (__fsub_rn(sec1, best1) < __fmaf_rn(1e-5f, S1b, 4e-5f)) {
            const int pos = atomicAdd(&g_nflag, 1);
            g_flag[pos] = n0 + r1;
        }
    }
}

// ---------------------------------------------------------------------------
// K3: bit-exact fallback for flagged pixels (1 warp per pixel).
// ---------------------------------------------------------------------------
__global__ void __launch_bounds__(256, 1)
vq_fallback(const float* __restrict__ x, const float* __restrict__ w,
            int* __restrict__ gidx, float* __restrict__ out_idx)
{
    if (blockIdx.x * 8 >= g_nflag) return;
    extern __shared__ char smc[];
    float* w_s   = (float*)smc;                          // [512*65] padded
    float* wsq_s = (float*)(smc + KC * 65 * 4);          // [512]
    float* xrow  = (float*)(smc + KC * 65 * 4 + KC * 4); // [8][64]
    const int tid = threadIdx.x, wid = tid >> 5, lane = tid & 31;

    for (int i = tid; i < KC * DD; i += 256) {
        const int k = i >> 6, d = i & 63;
        w_s[k * 65 + d] = w[i];
    }
    for (int i = tid; i < KC; i += 256) wsq_s[i] = g_wsq[i];
    __syncthreads();

    const int nflag = g_nflag;
    for (int f = blockIdx.x * 8 + wid; f < nflag; f += gridDim.x * 8) {
        const int n  = g_flag[f];
        const int b  = n >> 12, hw = n & 4095;
        const float* xp = x + (size_t)b * DD * HW + hw;
        xrow[wid * 64 + lane]      = xp[(size_t)lane * HW];
        xrow[wid * 64 + lane + 32] = xp[(size_t)(lane + 32) * HW];
        __syncwarp();
        float pa = __fmul_rn(xrow[wid * 64 + 2 * lane],     xrow[wid * 64 + 2 * lane]);
        float pb = __fmul_rn(xrow[wid * 64 + 2 * lane + 1], xrow[wid * 64 + 2 * lane + 1]);
        float pt = __fadd_rn(pa, pb);
#pragma unroll
        for (int off = 16; off >= 1; off >>= 1) {
            const float q = __shfl_down_sync(0xffffffffu, pt, off);
            pt = __fadd_rn(pt, q);
        }
        const float xsq = __shfl_sync(0xffffffffu, pt, 0);

        float bd = 3.4e38f; int bk = 0;
#pragma unroll 1
        for (int j = 0; j < 16; j++) {
            const int k = lane + 32 * j;
            float dot = 0.f;
#pragma unroll
            for (int d = 0; d < DD; d++)
                dot = __fmaf_rn(xrow[wid * 64 + d], w_s[k * 65 + d], dot);
            const float dist = __fsub_rn(__fadd_rn(xsq, wsq_s[k]), __fadd_rn(dot, dot));
            if (dist < bd) { bd = dist; bk = k; }
        }
#pragma unroll
        for (int off = 16; off >= 1; off >>= 1) {
            const float od = __shfl_down_sync(0xffffffffu, bd, off);
            const int   ok = __shfl_down_sync(0xffffffffu, bk, off);
            if (od < bd || (od == bd && ok < bk)) { bd = od; bk = ok; }
        }
        if (lane == 0) { gidx[n] = bk; out_idx[n] = (float)bk; }
        __syncwarp();
    }
}

// ---------------------------------------------------------------------------
// K4: quantized NCHW output (straight-through rounding), one-hot set, loss.
// No SMEM codebook — gather w rows via L2 (__ldg float4), high occupancy.
// ---------------------------------------------------------------------------
__global__ void __launch_bounds__(256)
vq_scatter(const float* __restrict__ x, const float* __restrict__ w,
           const int* __restrict__ gidx,
           float* __restrict__ out_q, float* __restrict__ out_enc,
           double* __restrict__ losssum)
{
    const int tid = threadIdx.x;
    const int n   = blockIdx.x * 256 + tid;
    const int k   = gidx[n];
    const int b   = n >> 12, hw = n & 4095;
    const float*  xp = x     + (size_t)b * DD * HW + hw;
    float*        qp = out_q + (size_t)b * DD * HW + hw;
    const float4* wr = (const float4*)(w + (size_t)k * DD);

    float s = 0.f;
#pragma unroll
    for (int j = 0; j < 16; j++) {
        const float4 wv = __ldg(wr + j);
        const float xv0 = xp[(size_t)(4 * j + 0) * HW];
        const float xv1 = xp[(size_t)(4 * j + 1) * HW];
        const float xv2 = xp[(size_t)(4 * j + 2) * HW];
        const float xv3 = xp[(size_t)(4 * j + 3) * HW];
        const float d0 = __fsub_rn(wv.x, xv0);
        const float d1 = __fsub_rn(wv.y, xv1);
        const float d2 = __fsub_rn(wv.z, xv2);
        const float d3 = __fsub_rn(wv.w, xv3);
        qp[(size_t)(4 * j + 0) * HW] = __fadd_rn(xv0, d0);
        qp[(size_t)(4 * j + 1) * HW] = __fadd_rn(xv1, d1);
        qp[(size_t)(4 * j + 2) * HW] = __fadd_rn(xv2, d2);
        qp[(size_t)(4 * j + 3) * HW] = __fadd_rn(xv3, d3);
        s = fmaf(d0, d0, s); s = fmaf(d1, d1, s);
        s = fmaf(d2, d2, s); s = fmaf(d3, d3, s);
    }
    out_enc[(size_t)n * KC + k] = 1.0f;

#pragma unroll
    for (int off = 16; off; off >>= 1) s += __shfl_down_sync(0xffffffffu, s, off);
    __shared__ float sred[8];
    if ((tid & 31) == 0) sred[tid >> 5] = s;
    __syncthreads();
    if (tid < 8) {
        float v = sred[tid];
#pragma unroll
        for (int off = 4; off; off >>= 1) v += __shfl_down_sync(0xffu, v, off);
        if (tid == 0) atomicAdd(losssum, (double)v);
    }
}

__global__ void vq_finalize(const double* __restrict__ losssum,
                            float* __restrict__ out_loss)
{
    out_loss[0] = (float)(2.0 * (*losssum) / (double)XNUM);
}

// ---------------------------------------------------------------------------
extern "C" void kernel_launch(void* const* d_in, const int* in_sizes, int n_in,
                              void* d_out, int out_size)
{
    const float* x = (const float*)d_in[0];   // [32, 64, 64, 64] NCHW
    const float* w = (const float*)d_in[1];   // [512, 64]

    float* out      = (float*)d_out;
    float* out_loss = out;
    float* out_q    = out + 1;
    float* out_enc  = out + 1 + (size_t)XNUM;
    float* out_idx  = out + 1 + (size_t)XNUM + (size_t)NPIX * KC;

    int*    gidx_ptr = nullptr;
    double* loss_ptr = nullptr;
    cudaGetSymbolAddress((void**)&gidx_ptr, g_idx);
    cudaGetSymbolAddress((void**)&loss_ptr, g_losssum);

    const int smem_fb = KC * 65 * 4 + KC * 4 + 8 * DD * 4;
    cudaFuncSetAttribute(vq_mma_filter, cudaFuncAttributeMaxDynamicSharedMemorySize, SM_TOT);
    cudaFuncSetAttribute(vq_fallback,   cudaFuncAttributeMaxDynamicSharedMemorySize, smem_fb);

    cudaMemsetAsync(loss_ptr, 0, sizeof(double), 0);

    vq_prep      <<<1, 512>>>(w);
    vq_mma_filter<<<NTILES, 256, SM_TOT>>>(x, w, gidx_ptr, out_idx, out_enc);
    vq_fallback  <<<64, 256, smem_fb>>>(x, w, gidx_ptr, out_idx);
    vq_scatter   <<<NPIX / 256, 256>>>(x, w, gidx_ptr, out_q, out_enc, loss_ptr);
    vq_finalize  <<<1, 1>>>(loss_ptr, out_loss);
}